// round 6
// baseline (speedup 1.0000x reference)
#include <cuda_runtime.h>
#include <cuda_bf16.h>
#include <cstdint>

#define NU 50000
#define NI 50000
#define NE 800000
#define HD 128

// ---------------- device scratch (no runtime allocation allowed) ----------------
__device__ __align__(16) float g_hu[(size_t)NU * HD];
__device__ __align__(16) float g_hi[(size_t)NI * HD];
__device__ __align__(16) float g_agg[(size_t)(NI + NU) * HD]; // [agg_item | agg_user]
__device__ __align__(16) float g_cnt[NI + NU];                // [cnt_item | cnt_user]
__device__ __align__(16) float g_z[(size_t)NU * 64];

// ---------------- zero ----------------
__global__ void zero_kernel(float4* __restrict__ p, int n4) {
    int i = blockIdx.x * blockDim.x + threadIdx.x;
    if (i < n4) p[i] = make_float4(0.f, 0.f, 0.f, 0.f);
}

// ---------------- degree count ----------------
__global__ void count_kernel(const int* __restrict__ dst, float* __restrict__ cnt, int ne) {
    int e = blockIdx.x * blockDim.x + threadIdx.x;
    if (e < ne) atomicAdd(&cnt[dst[e]], 1.0f);
}

// ---------------- edge scatter-sum: one warp per edge, red.v4.f32 ----------------
__global__ void __launch_bounds__(256) scatter_kernel(
    const float* __restrict__ src_feat, const int* __restrict__ ei,
    float* __restrict__ agg, int ne)
{
    int w = (blockIdx.x * blockDim.x + threadIdx.x) >> 5;
    int lane = threadIdx.x & 31;
    if (w >= ne) return;
    int s = __ldg(&ei[w]);
    int d = __ldg(&ei[ne + w]);
    const float4* sp = reinterpret_cast<const float4*>(src_feat + (size_t)s * HD);
    float4 v = sp[lane];
    float* dp = agg + (size_t)d * HD + lane * 4;
    asm volatile("red.global.add.v4.f32 [%0], {%1,%2,%3,%4};"
                 :: "l"(dp), "f"(v.x), "f"(v.y), "f"(v.z), "f"(v.w) : "memory");
}

// ---------------- fused SAGE combine ----------------
// h[r] = relu( (agg[r]/max(cnt,1)) @ Wl + bl + h[r] @ Wr, L2-normalized ) + h[r]
// BM=64 rows, BN=128 (full H), BK=16, 128 threads, 8x8 register tile.
__global__ void __launch_bounds__(128) combine_kernel(
    const float* __restrict__ agg, const float* __restrict__ cnt,
    float* __restrict__ h,
    const float* __restrict__ wl, const float* __restrict__ bl,
    const float* __restrict__ wr, int n)
{
    __shared__ float As[16 * 64];
    __shared__ float Xs[16 * 64];
    __shared__ float Wls[16 * 128];
    __shared__ float Wrs[16 * 128];
    __shared__ float sInv[64];

    const int tid  = threadIdx.x;
    const int tx   = tid & 15;   // col group: cols tx*8 .. +7
    const int ty   = tid >> 4;   // row group: rows ty*8 .. +7
    const int row0 = blockIdx.x * 64;

    if (tid < 64) {
        int r = row0 + tid;
        float c = (r < n) ? cnt[r] : 1.0f;
        sInv[tid] = 1.0f / fmaxf(c, 1.0f);
    }
    __syncthreads();

    float acc[8][8];
#pragma unroll
    for (int i = 0; i < 8; i++)
#pragma unroll
        for (int j = 0; j < 8; j++) acc[i][j] = 0.f;

    const int lrow  = tid >> 1;                 // 0..63
    const int lhalf = tid & 1;                  // k sub-offset 0 / 8
    const int grow  = min(row0 + lrow, n - 1);
    const float sc  = sInv[lrow];

    for (int kc = 0; kc < 8; kc++) {
        const int k0 = kc * 16;
        // stage weight chunks (contiguous 16x128)
        {
            const float4* sl = reinterpret_cast<const float4*>(wl + k0 * 128);
            const float4* sr = reinterpret_cast<const float4*>(wr + k0 * 128);
            float4* dl = reinterpret_cast<float4*>(Wls);
            float4* dr = reinterpret_cast<float4*>(Wrs);
#pragma unroll
            for (int i = 0; i < 4; i++) {
                dl[tid + i * 128] = sl[tid + i * 128];
                dr[tid + i * 128] = sr[tid + i * 128];
            }
        }
        // stage A (scaled) and X chunks, transposed to [k][row]
        {
            const float* ap = agg + (size_t)grow * HD + k0 + lhalf * 8;
            const float* xp = h   + (size_t)grow * HD + k0 + lhalf * 8;
            float4 a0 = *reinterpret_cast<const float4*>(ap);
            float4 a1 = *reinterpret_cast<const float4*>(ap + 4);
            float4 x0 = *reinterpret_cast<const float4*>(xp);
            float4 x1 = *reinterpret_cast<const float4*>(xp + 4);
            int kb = lhalf * 8;
            As[(kb + 0) * 64 + lrow] = a0.x * sc;
            As[(kb + 1) * 64 + lrow] = a0.y * sc;
            As[(kb + 2) * 64 + lrow] = a0.z * sc;
            As[(kb + 3) * 64 + lrow] = a0.w * sc;
            As[(kb + 4) * 64 + lrow] = a1.x * sc;
            As[(kb + 5) * 64 + lrow] = a1.y * sc;
            As[(kb + 6) * 64 + lrow] = a1.z * sc;
            As[(kb + 7) * 64 + lrow] = a1.w * sc;
            Xs[(kb + 0) * 64 + lrow] = x0.x;
            Xs[(kb + 1) * 64 + lrow] = x0.y;
            Xs[(kb + 2) * 64 + lrow] = x0.z;
            Xs[(kb + 3) * 64 + lrow] = x0.w;
            Xs[(kb + 4) * 64 + lrow] = x1.x;
            Xs[(kb + 5) * 64 + lrow] = x1.y;
            Xs[(kb + 6) * 64 + lrow] = x1.z;
            Xs[(kb + 7) * 64 + lrow] = x1.w;
        }
        __syncthreads();

#pragma unroll 2
        for (int k = 0; k < 16; k++) {
            float4 a0 = *reinterpret_cast<float4*>(&As[k * 64 + ty * 8]);
            float4 a1 = *reinterpret_cast<float4*>(&As[k * 64 + ty * 8 + 4]);
            float4 x0 = *reinterpret_cast<float4*>(&Xs[k * 64 + ty * 8]);
            float4 x1 = *reinterpret_cast<float4*>(&Xs[k * 64 + ty * 8 + 4]);
            float4 l0 = *reinterpret_cast<float4*>(&Wls[k * 128 + tx * 8]);
            float4 l1 = *reinterpret_cast<float4*>(&Wls[k * 128 + tx * 8 + 4]);
            float4 r0 = *reinterpret_cast<float4*>(&Wrs[k * 128 + tx * 8]);
            float4 r1 = *reinterpret_cast<float4*>(&Wrs[k * 128 + tx * 8 + 4]);
            float av[8] = {a0.x, a0.y, a0.z, a0.w, a1.x, a1.y, a1.z, a1.w};
            float xv[8] = {x0.x, x0.y, x0.z, x0.w, x1.x, x1.y, x1.z, x1.w};
            float lv[8] = {l0.x, l0.y, l0.z, l0.w, l1.x, l1.y, l1.z, l1.w};
            float rv[8] = {r0.x, r0.y, r0.z, r0.w, r1.x, r1.y, r1.z, r1.w};
#pragma unroll
            for (int i = 0; i < 8; i++)
#pragma unroll
                for (int j = 0; j < 8; j++) {
                    acc[i][j] = fmaf(av[i], lv[j], acc[i][j]);
                    acc[i][j] = fmaf(xv[i], rv[j], acc[i][j]);
                }
        }
        __syncthreads();
    }

    // epilogue: +bias, row L2-norm across the 16 tx lanes, relu, residual (in place)
    float bias[8];
#pragma unroll
    for (int j = 0; j < 8; j++) bias[j] = __ldg(&bl[tx * 8 + j]);

#pragma unroll
    for (int i = 0; i < 8; i++) {
        float v[8];
        float ss = 0.f;
#pragma unroll
        for (int j = 0; j < 8; j++) {
            v[j] = acc[i][j] + bias[j];
            ss = fmaf(v[j], v[j], ss);
        }
#pragma unroll
        for (int m = 8; m >= 1; m >>= 1)
            ss += __shfl_xor_sync(0xffffffffu, ss, m, 16);
        float inv = 1.0f / fmaxf(sqrtf(ss), 1e-12f);
        int gr = row0 + ty * 8 + i;
        if (gr < n) {
            float* hp = h + (size_t)gr * HD + tx * 8;
            float4 h0 = *reinterpret_cast<float4*>(hp);
            float4 h1 = *reinterpret_cast<float4*>(hp + 4);
            float o[8] = {h0.x, h0.y, h0.z, h0.w, h1.x, h1.y, h1.z, h1.w};
#pragma unroll
            for (int j = 0; j < 8; j++) o[j] += fmaxf(v[j] * inv, 0.0f);
            *reinterpret_cast<float4*>(hp)     = make_float4(o[0], o[1], o[2], o[3]);
            *reinterpret_cast<float4*>(hp + 4) = make_float4(o[4], o[5], o[6], o[7]);
        }
    }
}

// ---------------- generic dense + relu (encoders, head layer 1) ----------------
template<int K, int N, int ROWS>
__global__ void __launch_bounds__(256) dense_relu_kernel(
    const float* __restrict__ x, const float* __restrict__ W,
    const float* __restrict__ b, float* __restrict__ out, int n)
{
    constexpr int RPAR = 256 / N;
    __shared__ float Ws[K * N];
    __shared__ float Xs[ROWS * K];
    const int tid  = threadIdx.x;
    const int row0 = blockIdx.x * ROWS;

    for (int i = tid; i < K * N / 4; i += 256)
        reinterpret_cast<float4*>(Ws)[i] = reinterpret_cast<const float4*>(W)[i];
    for (int i = tid; i < ROWS * K / 4; i += 256) {
        int r = (i * 4) / K;
        int c = (i * 4) % K;
        int gr = min(row0 + r, n - 1);
        reinterpret_cast<float4*>(Xs)[i] =
            *reinterpret_cast<const float4*>(x + (size_t)gr * K + c);
    }
    __syncthreads();

    const int j  = tid % N;
    const int rp = tid / N;
    const float bias = __ldg(&b[j]);
    for (int r = rp; r < ROWS; r += RPAR) {
        float acc = bias;
#pragma unroll
        for (int k = 0; k < K; k++)
            acc = fmaf(Xs[r * K + k], Ws[k * N + j], acc);
        int gr = row0 + r;
        if (gr < n) out[(size_t)gr * N + j] = fmaxf(acc, 0.0f);
    }
}

// ---------------- head layer 2 (no relu): [n,64] @ [64,8] + b ----------------
__global__ void __launch_bounds__(256) head2_kernel(
    const float* __restrict__ z, const float* __restrict__ w2,
    const float* __restrict__ b2, float* __restrict__ out, int n)
{
    int idx = blockIdx.x * blockDim.x + threadIdx.x;
    if (idx >= n * 8) return;
    int row = idx >> 3;
    int j = idx & 7;
    float acc = __ldg(&b2[j]);
    const float* zr = z + (size_t)row * 64;
#pragma unroll
    for (int k = 0; k < 64; k++) acc = fmaf(zr[k], __ldg(&w2[k * 8 + j]), acc);
    out[idx] = acc;
}

// ---------------- launch ----------------
static float* sym_addr(const void* sym) {
    void* p = nullptr;
    cudaGetSymbolAddress(&p, sym);
    return reinterpret_cast<float*>(p);
}

extern "C" void kernel_launch(void* const* d_in, const int* in_sizes, int n_in,
                              void* d_out, int out_size)
{
    const float* x_user  = (const float*)d_in[0];
    const float* x_item  = (const float*)d_in[1];
    const int*   ei_u2i  = (const int*)d_in[2];
    const int*   ei_i2u  = (const int*)d_in[3];
    const float* enc_uw  = (const float*)d_in[4];
    const float* enc_ub  = (const float*)d_in[5];
    const float* enc_iw  = (const float*)d_in[6];
    const float* enc_ib  = (const float*)d_in[7];
    const float* L[12];
    for (int i = 0; i < 12; i++) L[i] = (const float*)d_in[8 + i];
    const float* head_w1 = (const float*)d_in[20];
    const float* head_b1 = (const float*)d_in[21];
    const float* head_w2 = (const float*)d_in[22];
    const float* head_b2 = (const float*)d_in[23];
    float* out = (float*)d_out;

    float* hu   = sym_addr(g_hu);
    float* hi   = sym_addr(g_hi);
    float* agg  = sym_addr(g_agg);
    float* cnt  = sym_addr(g_cnt);
    float* z    = sym_addr(g_z);
    float* agg_i = agg;
    float* agg_u = agg + (size_t)NI * HD;
    float* cnt_i = cnt;
    float* cnt_u = cnt + NI;

    // degrees (fixed across layers)
    {
        int n4 = (NI + NU) / 4;
        zero_kernel<<<(n4 + 255) / 256, 256>>>((float4*)cnt, n4);
        count_kernel<<<(NE + 255) / 256, 256>>>(ei_u2i + NE, cnt_i, NE);
        count_kernel<<<(NE + 255) / 256, 256>>>(ei_i2u + NE, cnt_u, NE);
    }

    // encoders
    dense_relu_kernel<64, 128, 16><<<(NU + 15) / 16, 256>>>(x_user, enc_uw, enc_ub, hu, NU);
    dense_relu_kernel<32, 128, 16><<<(NI + 15) / 16, 256>>>(x_item, enc_iw, enc_ib, hi, NI);

    const int scatter_blocks = (NE * 32 + 255) / 256;
    const int agg4 = (NI + NU) * HD / 4;

    for (int l = 0; l < 2; l++) {
        const float* wl_ui = L[l * 6 + 0];
        const float* bl_ui = L[l * 6 + 1];
        const float* wr_ui = L[l * 6 + 2];
        const float* wl_iu = L[l * 6 + 3];
        const float* bl_iu = L[l * 6 + 4];
        const float* wr_iu = L[l * 6 + 5];

        zero_kernel<<<(agg4 + 255) / 256, 256>>>((float4*)agg, agg4);
        // both scatters read OLD hu/hi before any in-place update
        scatter_kernel<<<scatter_blocks, 256>>>(hu, ei_u2i, agg_i, NE);
        scatter_kernel<<<scatter_blocks, 256>>>(hi, ei_i2u, agg_u, NE);
        // in-place: h_new = relu(norm(...)) + h_old
        combine_kernel<<<(NI + 63) / 64, 128>>>(agg_i, cnt_i, hi, wl_ui, bl_ui, wr_ui, NI);
        combine_kernel<<<(NU + 63) / 64, 128>>>(agg_u, cnt_u, hu, wl_iu, bl_iu, wr_iu, NU);
    }

    // head
    dense_relu_kernel<128, 64, 16><<<(NU + 15) / 16, 256>>>(hu, head_w1, head_b1, z, NU);
    head2_kernel<<<(NU * 8 + 255) / 256, 256>>>(z, head_w2, head_b2, out, NU);
}

// round 7
// speedup vs baseline: 1.0023x; 1.0023x over previous
#include <cuda_runtime.h>
#include <cuda_bf16.h>
#include <cstdint>

#define NU 50000
#define NI 50000
#define NE 800000
#define HD 128

// ---------------- device scratch (no runtime allocation allowed) ----------------
__device__ __align__(16) float g_hu[(size_t)NU * HD];
__device__ __align__(16) float g_hi[(size_t)NI * HD];
__device__ __align__(16) float g_agg[(size_t)(NI + NU) * HD]; // [agg_item | agg_user]
__device__ __align__(16) float g_cnt[NI + NU];                // [cnt_item | cnt_user]
__device__ __align__(16) float g_z[(size_t)NU * 64];

// ---------------- zero ----------------
__global__ void zero_kernel(float4* __restrict__ p, int n4) {
    int i = blockIdx.x * blockDim.x + threadIdx.x;
    if (i < n4) p[i] = make_float4(0.f, 0.f, 0.f, 0.f);
}

// ---------------- degree count ----------------
__global__ void count_kernel(const int* __restrict__ dst, float* __restrict__ cnt, int ne) {
    int e = blockIdx.x * blockDim.x + threadIdx.x;
    if (e < ne) atomicAdd(&cnt[dst[e]], 1.0f);
}

// ---------------- edge scatter-sum: one warp per edge, red.v4.f32 ----------------
__global__ void __launch_bounds__(256) scatter_kernel(
    const float* __restrict__ src_feat, const int* __restrict__ ei,
    float* __restrict__ agg, int ne)
{
    int w = (blockIdx.x * blockDim.x + threadIdx.x) >> 5;
    int lane = threadIdx.x & 31;
    if (w >= ne) return;
    int s = __ldg(&ei[w]);
    int d = __ldg(&ei[ne + w]);
    const float4* sp = reinterpret_cast<const float4*>(src_feat + (size_t)s * HD);
    float4 v = sp[lane];
    float* dp = agg + (size_t)d * HD + lane * 4;
    asm volatile("red.global.add.v4.f32 [%0], {%1,%2,%3,%4};"
                 :: "l"(dp), "f"(v.x), "f"(v.y), "f"(v.z), "f"(v.w) : "memory");
}

// ---------------- fused SAGE combine ----------------
// h[r] = relu( (agg[r]/max(cnt,1)) @ Wl + bl + h[r] @ Wr, L2-normalized ) + h[r]
// BM=64 rows, BN=128 (full H), BK=16, 128 threads, 8x8 register tile.
__global__ void __launch_bounds__(128) combine_kernel(
    const float* __restrict__ agg, const float* __restrict__ cnt,
    float* __restrict__ h,
    const float* __restrict__ wl, const float* __restrict__ bl,
    const float* __restrict__ wr, int n)
{
    __shared__ float As[16 * 64];
    __shared__ float Xs[16 * 64];
    __shared__ float Wls[16 * 128];
    __shared__ float Wrs[16 * 128];
    __shared__ float sInv[64];

    const int tid  = threadIdx.x;
    const int tx   = tid & 15;   // col group: cols tx*8 .. +7
    const int ty   = tid >> 4;   // row group: rows ty*8 .. +7
    const int row0 = blockIdx.x * 64;

    if (tid < 64) {
        int r = row0 + tid;
        float c = (r < n) ? cnt[r] : 1.0f;
        sInv[tid] = 1.0f / fmaxf(c, 1.0f);
    }
    __syncthreads();

    float acc[8][8];
#pragma unroll
    for (int i = 0; i < 8; i++)
#pragma unroll
        for (int j = 0; j < 8; j++) acc[i][j] = 0.f;

    const int lrow  = tid >> 1;                 // 0..63
    const int lhalf = tid & 1;                  // k sub-offset 0 / 8
    const int grow  = min(row0 + lrow, n - 1);
    const float sc  = sInv[lrow];

    for (int kc = 0; kc < 8; kc++) {
        const int k0 = kc * 16;
        // stage weight chunks (contiguous 16x128)
        {
            const float4* sl = reinterpret_cast<const float4*>(wl + k0 * 128);
            const float4* sr = reinterpret_cast<const float4*>(wr + k0 * 128);
            float4* dl = reinterpret_cast<float4*>(Wls);
            float4* dr = reinterpret_cast<float4*>(Wrs);
#pragma unroll
            for (int i = 0; i < 4; i++) {
                dl[tid + i * 128] = sl[tid + i * 128];
                dr[tid + i * 128] = sr[tid + i * 128];
            }
        }
        // stage A (scaled) and X chunks, transposed to [k][row]
        {
            const float* ap = agg + (size_t)grow * HD + k0 + lhalf * 8;
            const float* xp = h   + (size_t)grow * HD + k0 + lhalf * 8;
            float4 a0 = *reinterpret_cast<const float4*>(ap);
            float4 a1 = *reinterpret_cast<const float4*>(ap + 4);
            float4 x0 = *reinterpret_cast<const float4*>(xp);
            float4 x1 = *reinterpret_cast<const float4*>(xp + 4);
            int kb = lhalf * 8;
            As[(kb + 0) * 64 + lrow] = a0.x * sc;
            As[(kb + 1) * 64 + lrow] = a0.y * sc;
            As[(kb + 2) * 64 + lrow] = a0.z * sc;
            As[(kb + 3) * 64 + lrow] = a0.w * sc;
            As[(kb + 4) * 64 + lrow] = a1.x * sc;
            As[(kb + 5) * 64 + lrow] = a1.y * sc;
            As[(kb + 6) * 64 + lrow] = a1.z * sc;
            As[(kb + 7) * 64 + lrow] = a1.w * sc;
            Xs[(kb + 0) * 64 + lrow] = x0.x;
            Xs[(kb + 1) * 64 + lrow] = x0.y;
            Xs[(kb + 2) * 64 + lrow] = x0.z;
            Xs[(kb + 3) * 64 + lrow] = x0.w;
            Xs[(kb + 4) * 64 + lrow] = x1.x;
            Xs[(kb + 5) * 64 + lrow] = x1.y;
            Xs[(kb + 6) * 64 + lrow] = x1.z;
            Xs[(kb + 7) * 64 + lrow] = x1.w;
        }
        __syncthreads();

#pragma unroll 2
        for (int k = 0; k < 16; k++) {
            float4 a0 = *reinterpret_cast<float4*>(&As[k * 64 + ty * 8]);
            float4 a1 = *reinterpret_cast<float4*>(&As[k * 64 + ty * 8 + 4]);
            float4 x0 = *reinterpret_cast<float4*>(&Xs[k * 64 + ty * 8]);
            float4 x1 = *reinterpret_cast<float4*>(&Xs[k * 64 + ty * 8 + 4]);
            float4 l0 = *reinterpret_cast<float4*>(&Wls[k * 128 + tx * 8]);
            float4 l1 = *reinterpret_cast<float4*>(&Wls[k * 128 + tx * 8 + 4]);
            float4 r0 = *reinterpret_cast<float4*>(&Wrs[k * 128 + tx * 8]);
            float4 r1 = *reinterpret_cast<float4*>(&Wrs[k * 128 + tx * 8 + 4]);
            float av[8] = {a0.x, a0.y, a0.z, a0.w, a1.x, a1.y, a1.z, a1.w};
            float xv[8] = {x0.x, x0.y, x0.z, x0.w, x1.x, x1.y, x1.z, x1.w};
            float lv[8] = {l0.x, l0.y, l0.z, l0.w, l1.x, l1.y, l1.z, l1.w};
            float rv[8] = {r0.x, r0.y, r0.z, r0.w, r1.x, r1.y, r1.z, r1.w};
#pragma unroll
            for (int i = 0; i < 8; i++)
#pragma unroll
                for (int j = 0; j < 8; j++) {
                    acc[i][j] = fmaf(av[i], lv[j], acc[i][j]);
                    acc[i][j] = fmaf(xv[i], rv[j], acc[i][j]);
                }
        }
        __syncthreads();
    }

    // epilogue: +bias, row L2-norm across the 16 tx lanes, relu, residual (in place)
    float bias[8];
#pragma unroll
    for (int j = 0; j < 8; j++) bias[j] = __ldg(&bl[tx * 8 + j]);

#pragma unroll
    for (int i = 0; i < 8; i++) {
        float v[8];
        float ss = 0.f;
#pragma unroll
        for (int j = 0; j < 8; j++) {
            v[j] = acc[i][j] + bias[j];
            ss = fmaf(v[j], v[j], ss);
        }
#pragma unroll
        for (int m = 8; m >= 1; m >>= 1)
            ss += __shfl_xor_sync(0xffffffffu, ss, m, 16);
        float inv = 1.0f / fmaxf(sqrtf(ss), 1e-12f);
        int gr = row0 + ty * 8 + i;
        if (gr < n) {
            float* hp = h + (size_t)gr * HD + tx * 8;
            float4 h0 = *reinterpret_cast<float4*>(hp);
            float4 h1 = *reinterpret_cast<float4*>(hp + 4);
            float o[8] = {h0.x, h0.y, h0.z, h0.w, h1.x, h1.y, h1.z, h1.w};
#pragma unroll
            for (int j = 0; j < 8; j++) o[j] += fmaxf(v[j] * inv, 0.0f);
            *reinterpret_cast<float4*>(hp)     = make_float4(o[0], o[1], o[2], o[3]);
            *reinterpret_cast<float4*>(hp + 4) = make_float4(o[4], o[5], o[6], o[7]);
        }
    }
}

// ---------------- generic dense + relu (encoders, head layer 1) ----------------
template<int K, int N, int ROWS>
__global__ void __launch_bounds__(256) dense_relu_kernel(
    const float* __restrict__ x, const float* __restrict__ W,
    const float* __restrict__ b, float* __restrict__ out, int n)
{
    constexpr int RPAR = 256 / N;
    __shared__ float Ws[K * N];
    __shared__ float Xs[ROWS * K];
    const int tid  = threadIdx.x;
    const int row0 = blockIdx.x * ROWS;

    for (int i = tid; i < K * N / 4; i += 256)
        reinterpret_cast<float4*>(Ws)[i] = reinterpret_cast<const float4*>(W)[i];
    for (int i = tid; i < ROWS * K / 4; i += 256) {
        int r = (i * 4) / K;
        int c = (i * 4) % K;
        int gr = min(row0 + r, n - 1);
        reinterpret_cast<float4*>(Xs)[i] =
            *reinterpret_cast<const float4*>(x + (size_t)gr * K + c);
    }
    __syncthreads();

    const int j  = tid % N;
    const int rp = tid / N;
    const float bias = __ldg(&b[j]);
    for (int r = rp; r < ROWS; r += RPAR) {
        float acc = bias;
#pragma unroll
        for (int k = 0; k < K; k++)
            acc = fmaf(Xs[r * K + k], Ws[k * N + j], acc);
        int gr = row0 + r;
        if (gr < n) out[(size_t)gr * N + j] = fmaxf(acc, 0.0f);
    }
}

// ---------------- head layer 2 (no relu): [n,64] @ [64,8] + b ----------------
__global__ void __launch_bounds__(256) head2_kernel(
    const float* __restrict__ z, const float* __restrict__ w2,
    const float* __restrict__ b2, float* __restrict__ out, int n)
{
    int idx = blockIdx.x * blockDim.x + threadIdx.x;
    if (idx >= n * 8) return;
    int row = idx >> 3;
    int j = idx & 7;
    float acc = __ldg(&b2[j]);
    const float* zr = z + (size_t)row * 64;
#pragma unroll
    for (int k = 0; k < 64; k++) acc = fmaf(zr[k], __ldg(&w2[k * 8 + j]), acc);
    out[idx] = acc;
}

// ---------------- launch ----------------
static float* sym_addr(const void* sym) {
    void* p = nullptr;
    cudaGetSymbolAddress(&p, sym);
    return reinterpret_cast<float*>(p);
}

extern "C" void kernel_launch(void* const* d_in, const int* in_sizes, int n_in,
                              void* d_out, int out_size)
{
    const float* x_user  = (const float*)d_in[0];
    const float* x_item  = (const float*)d_in[1];
    const int*   ei_u2i  = (const int*)d_in[2];
    const int*   ei_i2u  = (const int*)d_in[3];
    const float* enc_uw  = (const float*)d_in[4];
    const float* enc_ub  = (const float*)d_in[5];
    const float* enc_iw  = (const float*)d_in[6];
    const float* enc_ib  = (const float*)d_in[7];
    const float* L[12];
    for (int i = 0; i < 12; i++) L[i] = (const float*)d_in[8 + i];
    const float* head_w1 = (const float*)d_in[20];
    const float* head_b1 = (const float*)d_in[21];
    const float* head_w2 = (const float*)d_in[22];
    const float* head_b2 = (const float*)d_in[23];
    float* out = (float*)d_out;

    float* hu   = sym_addr(g_hu);
    float* hi   = sym_addr(g_hi);
    float* agg  = sym_addr(g_agg);
    float* cnt  = sym_addr(g_cnt);
    float* z    = sym_addr(g_z);
    float* agg_i = agg;
    float* agg_u = agg + (size_t)NI * HD;
    float* cnt_i = cnt;
    float* cnt_u = cnt + NI;

    // degrees (fixed across layers)
    {
        int n4 = (NI + NU) / 4;
        zero_kernel<<<(n4 + 255) / 256, 256>>>((float4*)cnt, n4);
        count_kernel<<<(NE + 255) / 256, 256>>>(ei_u2i + NE, cnt_i, NE);
        count_kernel<<<(NE + 255) / 256, 256>>>(ei_i2u + NE, cnt_u, NE);
    }

    // encoders
    dense_relu_kernel<64, 128, 16><<<(NU + 15) / 16, 256>>>(x_user, enc_uw, enc_ub, hu, NU);
    dense_relu_kernel<32, 128, 16><<<(NI + 15) / 16, 256>>>(x_item, enc_iw, enc_ib, hi, NI);

    const int scatter_blocks = (NE * 32 + 255) / 256;
    const int agg4 = (NI + NU) * HD / 4;

    for (int l = 0; l < 2; l++) {
        const float* wl_ui = L[l * 6 + 0];
        const float* bl_ui = L[l * 6 + 1];
        const float* wr_ui = L[l * 6 + 2];
        const float* wl_iu = L[l * 6 + 3];
        const float* bl_iu = L[l * 6 + 4];
        const float* wr_iu = L[l * 6 + 5];

        zero_kernel<<<(agg4 + 255) / 256, 256>>>((float4*)agg, agg4);
        // both scatters read OLD hu/hi before any in-place update
        scatter_kernel<<<scatter_blocks, 256>>>(hu, ei_u2i, agg_i, NE);
        scatter_kernel<<<scatter_blocks, 256>>>(hi, ei_i2u, agg_u, NE);
        // in-place: h_new = relu(norm(...)) + h_old
        combine_kernel<<<(NI + 63) / 64, 128>>>(agg_i, cnt_i, hi, wl_ui, bl_ui, wr_ui, NI);
        combine_kernel<<<(NU + 63) / 64, 128>>>(agg_u, cnt_u, hu, wl_iu, bl_iu, wr_iu, NU);
    }

    // head
    dense_relu_kernel<128, 64, 16><<<(NU + 15) / 16, 256>>>(hu, head_w1, head_b1, z, NU);
    head2_kernel<<<(NU * 8 + 255) / 256, 256>>>(z, head_w2, head_b2, out, NU);
}

// round 8
// speedup vs baseline: 1.3187x; 1.3158x over previous
#include <cuda_runtime.h>
#include <cuda_bf16.h>
#include <cstdint>

#define NU 50000
#define NI 50000
#define NE 800000
#define HD 128

// ---------------- device scratch (no runtime allocation allowed) ----------------
__device__ __align__(16) float g_hu[(size_t)NU * HD];
__device__ __align__(16) float g_hi[(size_t)NI * HD];
__device__ __align__(16) float g_agg[(size_t)(NI + NU) * HD]; // [agg_item | agg_user]
__device__ __align__(16) float g_z[(size_t)NU * 64];

// CSR scratch
__device__ __align__(16) int g_deg[NI + NU];        // [deg_item | deg_user]
__device__ __align__(16) int g_rowptr_i[NI + 1];
__device__ __align__(16) int g_rowptr_u[NU + 1];
__device__ __align__(16) int g_fill[NI + NU];       // running fill offsets
__device__ __align__(16) int g_esrc_i[NE];          // src user ids grouped by dst item
__device__ __align__(16) int g_esrc_u[NE];          // src item ids grouped by dst user

// ---------------- zero ----------------
__global__ void zero_kernel(float4* __restrict__ p, int n4) {
    int i = blockIdx.x * blockDim.x + threadIdx.x;
    if (i < n4) p[i] = make_float4(0.f, 0.f, 0.f, 0.f);
}

// ---------------- CSR build: histogram ----------------
__global__ void hist_kernel(const int* __restrict__ dst, int* __restrict__ deg, int ne) {
    int e = blockIdx.x * blockDim.x + threadIdx.x;
    if (e < ne) atomicAdd(&deg[dst[e]], 1);
}

// ---------------- CSR build: single-block exclusive scan ----------------
__global__ void __launch_bounds__(1024) scan_kernel(
    const int* __restrict__ cnt, int* __restrict__ rowptr, int n)
{
    __shared__ int carry;
    __shared__ int warp_sums[32];
    const int tid = threadIdx.x;
    const int lane = tid & 31;
    if (tid == 0) carry = 0;
    __syncthreads();
    for (int base = 0; base < n; base += 1024) {
        int i = base + tid;
        int v = (i < n) ? cnt[i] : 0;
        int x = v;
#pragma unroll
        for (int off = 1; off < 32; off <<= 1) {
            int y = __shfl_up_sync(0xffffffffu, x, off);
            if (lane >= off) x += y;
        }
        if (lane == 31) warp_sums[tid >> 5] = x;
        __syncthreads();
        if (tid < 32) {
            int s = warp_sums[tid];
#pragma unroll
            for (int off = 1; off < 32; off <<= 1) {
                int y = __shfl_up_sync(0xffffffffu, s, off);
                if (tid >= off) s += y;
            }
            warp_sums[tid] = s;
        }
        __syncthreads();
        int prev = (tid >= 32) ? warp_sums[(tid >> 5) - 1] : 0;
        int incl = x + prev;
        if (i < n) rowptr[i] = carry + incl - v;
        int chunk_total = warp_sums[31];
        __syncthreads();   // everyone has read carry + warp_sums
        if (tid == 0) carry += chunk_total;
        __syncthreads();
    }
    if (tid == 0) rowptr[n] = carry;
}

// ---------------- CSR build: copy rowptr -> fill cursor ----------------
__global__ void copy_kernel(const int* __restrict__ src, int* __restrict__ dst, int n) {
    int i = blockIdx.x * blockDim.x + threadIdx.x;
    if (i < n) dst[i] = src[i];
}

// ---------------- CSR build: fill edge-source buckets ----------------
__global__ void fill_kernel(const int* __restrict__ ei, int* __restrict__ cursor,
                            int* __restrict__ esrc, int ne)
{
    int e = blockIdx.x * blockDim.x + threadIdx.x;
    if (e < ne) {
        int d = ei[ne + e];
        int p = atomicAdd(&cursor[d], 1);
        esrc[p] = ei[e];
    }
}

// ---------------- gather mean aggregation: one warp per dst node ----------------
__global__ void __launch_bounds__(256) gather_mean_kernel(
    const float* __restrict__ src_feat, const int* __restrict__ rowptr,
    const int* __restrict__ esrc, float* __restrict__ agg, int n)
{
    int node = (blockIdx.x * blockDim.x + threadIdx.x) >> 5;
    int lane = threadIdx.x & 31;
    if (node >= n) return;
    int beg = __ldg(&rowptr[node]);
    int end = __ldg(&rowptr[node + 1]);
    float4 acc = make_float4(0.f, 0.f, 0.f, 0.f);
    int e = beg;
    for (; e + 4 <= end; e += 4) {
        int s0 = __ldg(&esrc[e]);
        int s1 = __ldg(&esrc[e + 1]);
        int s2 = __ldg(&esrc[e + 2]);
        int s3 = __ldg(&esrc[e + 3]);
        float4 v0 = reinterpret_cast<const float4*>(src_feat + (size_t)s0 * HD)[lane];
        float4 v1 = reinterpret_cast<const float4*>(src_feat + (size_t)s1 * HD)[lane];
        float4 v2 = reinterpret_cast<const float4*>(src_feat + (size_t)s2 * HD)[lane];
        float4 v3 = reinterpret_cast<const float4*>(src_feat + (size_t)s3 * HD)[lane];
        acc.x += (v0.x + v1.x) + (v2.x + v3.x);
        acc.y += (v0.y + v1.y) + (v2.y + v3.y);
        acc.z += (v0.z + v1.z) + (v2.z + v3.z);
        acc.w += (v0.w + v1.w) + (v2.w + v3.w);
    }
    for (; e < end; e++) {
        int s = __ldg(&esrc[e]);
        float4 v = reinterpret_cast<const float4*>(src_feat + (size_t)s * HD)[lane];
        acc.x += v.x; acc.y += v.y; acc.z += v.z; acc.w += v.w;
    }
    float inv = 1.0f / fmaxf((float)(end - beg), 1.0f);
    acc.x *= inv; acc.y *= inv; acc.z *= inv; acc.w *= inv;
    reinterpret_cast<float4*>(agg + (size_t)node * HD)[lane] = acc;
}

// ---------------- fused SAGE combine ----------------
// h[r] = relu( L2norm(agg[r] @ Wl + bl + h[r] @ Wr) ) + h[r]
// BM=64 rows, BN=128 (full H), BK=16, 128 threads, 8x8 register tile.
// agg already holds the MEAN (no per-row scaling needed).
__global__ void __launch_bounds__(128) combine_kernel(
    const float* __restrict__ agg, float* __restrict__ h,
    const float* __restrict__ wl, const float* __restrict__ bl,
    const float* __restrict__ wr, int n)
{
    __shared__ float As[16 * 64];
    __shared__ float Xs[16 * 64];
    __shared__ float Wls[16 * 128];
    __shared__ float Wrs[16 * 128];

    const int tid  = threadIdx.x;
    const int tx   = tid & 15;   // col group: cols tx*8 .. +7
    const int ty   = tid >> 4;   // row group: rows ty*8 .. +7
    const int row0 = blockIdx.x * 64;

    float acc[8][8];
#pragma unroll
    for (int i = 0; i < 8; i++)
#pragma unroll
        for (int j = 0; j < 8; j++) acc[i][j] = 0.f;

    const int lrow  = tid >> 1;                 // 0..63
    const int lhalf = tid & 1;                  // k sub-offset 0 / 8
    const int grow  = min(row0 + lrow, n - 1);

    for (int kc = 0; kc < 8; kc++) {
        const int k0 = kc * 16;
        // stage weight chunks (contiguous 16x128)
        {
            const float4* sl = reinterpret_cast<const float4*>(wl + k0 * 128);
            const float4* sr = reinterpret_cast<const float4*>(wr + k0 * 128);
            float4* dl = reinterpret_cast<float4*>(Wls);
            float4* dr = reinterpret_cast<float4*>(Wrs);
#pragma unroll
            for (int i = 0; i < 4; i++) {
                dl[tid + i * 128] = sl[tid + i * 128];
                dr[tid + i * 128] = sr[tid + i * 128];
            }
        }
        // stage A and X chunks, transposed to [k][row]
        {
            const float* ap = agg + (size_t)grow * HD + k0 + lhalf * 8;
            const float* xp = h   + (size_t)grow * HD + k0 + lhalf * 8;
            float4 a0 = *reinterpret_cast<const float4*>(ap);
            float4 a1 = *reinterpret_cast<const float4*>(ap + 4);
            float4 x0 = *reinterpret_cast<const float4*>(xp);
            float4 x1 = *reinterpret_cast<const float4*>(xp + 4);
            int kb = lhalf * 8;
            As[(kb + 0) * 64 + lrow] = a0.x;
            As[(kb + 1) * 64 + lrow] = a0.y;
            As[(kb + 2) * 64 + lrow] = a0.z;
            As[(kb + 3) * 64 + lrow] = a0.w;
            As[(kb + 4) * 64 + lrow] = a1.x;
            As[(kb + 5) * 64 + lrow] = a1.y;
            As[(kb + 6) * 64 + lrow] = a1.z;
            As[(kb + 7) * 64 + lrow] = a1.w;
            Xs[(kb + 0) * 64 + lrow] = x0.x;
            Xs[(kb + 1) * 64 + lrow] = x0.y;
            Xs[(kb + 2) * 64 + lrow] = x0.z;
            Xs[(kb + 3) * 64 + lrow] = x0.w;
            Xs[(kb + 4) * 64 + lrow] = x1.x;
            Xs[(kb + 5) * 64 + lrow] = x1.y;
            Xs[(kb + 6) * 64 + lrow] = x1.z;
            Xs[(kb + 7) * 64 + lrow] = x1.w;
        }
        __syncthreads();

#pragma unroll 2
        for (int k = 0; k < 16; k++) {
            float4 a0 = *reinterpret_cast<float4*>(&As[k * 64 + ty * 8]);
            float4 a1 = *reinterpret_cast<float4*>(&As[k * 64 + ty * 8 + 4]);
            float4 x0 = *reinterpret_cast<float4*>(&Xs[k * 64 + ty * 8]);
            float4 x1 = *reinterpret_cast<float4*>(&Xs[k * 64 + ty * 8 + 4]);
            float4 l0 = *reinterpret_cast<float4*>(&Wls[k * 128 + tx * 8]);
            float4 l1 = *reinterpret_cast<float4*>(&Wls[k * 128 + tx * 8 + 4]);
            float4 r0 = *reinterpret_cast<float4*>(&Wrs[k * 128 + tx * 8]);
            float4 r1 = *reinterpret_cast<float4*>(&Wrs[k * 128 + tx * 8 + 4]);
            float av[8] = {a0.x, a0.y, a0.z, a0.w, a1.x, a1.y, a1.z, a1.w};
            float xv[8] = {x0.x, x0.y, x0.z, x0.w, x1.x, x1.y, x1.z, x1.w};
            float lv[8] = {l0.x, l0.y, l0.z, l0.w, l1.x, l1.y, l1.z, l1.w};
            float rv[8] = {r0.x, r0.y, r0.z, r0.w, r1.x, r1.y, r1.z, r1.w};
#pragma unroll
            for (int i = 0; i < 8; i++)
#pragma unroll
                for (int j = 0; j < 8; j++) {
                    acc[i][j] = fmaf(av[i], lv[j], acc[i][j]);
                    acc[i][j] = fmaf(xv[i], rv[j], acc[i][j]);
                }
        }
        __syncthreads();
    }

    // epilogue: +bias, row L2-norm across the 16 tx lanes, relu, residual (in place)
    float bias[8];
#pragma unroll
    for (int j = 0; j < 8; j++) bias[j] = __ldg(&bl[tx * 8 + j]);

#pragma unroll
    for (int i = 0; i < 8; i++) {
        float v[8];
        float ss = 0.f;
#pragma unroll
        for (int j = 0; j < 8; j++) {
            v[j] = acc[i][j] + bias[j];
            ss = fmaf(v[j], v[j], ss);
        }
#pragma unroll
        for (int m = 8; m >= 1; m >>= 1)
            ss += __shfl_xor_sync(0xffffffffu, ss, m, 16);
        float inv = 1.0f / fmaxf(sqrtf(ss), 1e-12f);
        int gr = row0 + ty * 8 + i;
        if (gr < n) {
            float* hp = h + (size_t)gr * HD + tx * 8;
            float4 h0 = *reinterpret_cast<float4*>(hp);
            float4 h1 = *reinterpret_cast<float4*>(hp + 4);
            float o[8] = {h0.x, h0.y, h0.z, h0.w, h1.x, h1.y, h1.z, h1.w};
#pragma unroll
            for (int j = 0; j < 8; j++) o[j] += fmaxf(v[j] * inv, 0.0f);
            *reinterpret_cast<float4*>(hp)     = make_float4(o[0], o[1], o[2], o[3]);
            *reinterpret_cast<float4*>(hp + 4) = make_float4(o[4], o[5], o[6], o[7]);
        }
    }
}

// ---------------- register-tiled dense + relu (encoders, head layer 1) ----------------
// out[n,N] = relu(x[n,K] @ W[K,N] + b). 128 threads, 8x8 register tile per thread.
// N=128: 64-row blocks; N=64: 128-row blocks.
template<int K, int N>
__global__ void __launch_bounds__(128) mlp_relu_kernel(
    const float* __restrict__ x, const float* __restrict__ W,
    const float* __restrict__ b, float* __restrict__ out, int n)
{
    constexpr int TX = N / 8;        // col groups (16 or 8)
    constexpr int TY = 128 / TX;     // row groups (8 or 16)
    constexpr int BM = TY * 8;       // rows per block (64 or 128)
    __shared__ float Xs[16 * BM];
    __shared__ float Ws[16 * N];

    const int tid  = threadIdx.x;
    const int tx   = tid % TX;
    const int ty   = tid / TX;
    const int row0 = blockIdx.x * BM;

    float acc[8][8];
#pragma unroll
    for (int i = 0; i < 8; i++)
#pragma unroll
        for (int j = 0; j < 8; j++) acc[i][j] = 0.f;

#pragma unroll 1
    for (int kc = 0; kc < K / 16; kc++) {
        const int k0 = kc * 16;
        // stage W chunk (16 x N, contiguous)
#pragma unroll
        for (int i = tid; i < 16 * N / 4; i += 128)
            reinterpret_cast<float4*>(Ws)[i] =
                reinterpret_cast<const float4*>(W + (size_t)k0 * N)[i];
        // stage X chunk transposed to [k][row]
#pragma unroll
        for (int idx = tid; idx < BM * 2; idx += 128) {
            int r = idx >> 1, half = idx & 1;
            int gr = min(row0 + r, n - 1);
            const float* xp = x + (size_t)gr * K + k0 + half * 8;
            float4 x0 = *reinterpret_cast<const float4*>(xp);
            float4 x1 = *reinterpret_cast<const float4*>(xp + 4);
            int kb = half * 8;
            Xs[(kb + 0) * BM + r] = x0.x;
            Xs[(kb + 1) * BM + r] = x0.y;
            Xs[(kb + 2) * BM + r] = x0.z;
            Xs[(kb + 3) * BM + r] = x0.w;
            Xs[(kb + 4) * BM + r] = x1.x;
            Xs[(kb + 5) * BM + r] = x1.y;
            Xs[(kb + 6) * BM + r] = x1.z;
            Xs[(kb + 7) * BM + r] = x1.w;
        }
        __syncthreads();

#pragma unroll 2
        for (int k = 0; k < 16; k++) {
            float4 a0 = *reinterpret_cast<float4*>(&Xs[k * BM + ty * 8]);
            float4 a1 = *reinterpret_cast<float4*>(&Xs[k * BM + ty * 8 + 4]);
            float4 w0 = *reinterpret_cast<float4*>(&Ws[k * N + tx * 8]);
            float4 w1 = *reinterpret_cast<float4*>(&Ws[k * N + tx * 8 + 4]);
            float av[8] = {a0.x, a0.y, a0.z, a0.w, a1.x, a1.y, a1.z, a1.w};
            float wv[8] = {w0.x, w0.y, w0.z, w0.w, w1.x, w1.y, w1.z, w1.w};
#pragma unroll
            for (int i = 0; i < 8; i++)
#pragma unroll
                for (int j = 0; j < 8; j++)
                    acc[i][j] = fmaf(av[i], wv[j], acc[i][j]);
        }
        __syncthreads();
    }

    float bias[8];
#pragma unroll
    for (int j = 0; j < 8; j++) bias[j] = __ldg(&b[tx * 8 + j]);

#pragma unroll
    for (int i = 0; i < 8; i++) {
        int gr = row0 + ty * 8 + i;
        if (gr < n) {
            float o[8];
#pragma unroll
            for (int j = 0; j < 8; j++) o[j] = fmaxf(acc[i][j] + bias[j], 0.0f);
            float* op = out + (size_t)gr * N + tx * 8;
            *reinterpret_cast<float4*>(op)     = make_float4(o[0], o[1], o[2], o[3]);
            *reinterpret_cast<float4*>(op + 4) = make_float4(o[4], o[5], o[6], o[7]);
        }
    }
}

// ---------------- head layer 2 (no relu): [n,64] @ [64,8] + b ----------------
__global__ void __launch_bounds__(256) head2_kernel(
    const float* __restrict__ z, const float* __restrict__ w2,
    const float* __restrict__ b2, float* __restrict__ out, int n)
{
    int idx = blockIdx.x * blockDim.x + threadIdx.x;
    if (idx >= n * 8) return;
    int row = idx >> 3;
    int j = idx & 7;
    float acc = __ldg(&b2[j]);
    const float* zr = z + (size_t)row * 64;
#pragma unroll
    for (int k = 0; k < 64; k++) acc = fmaf(zr[k], __ldg(&w2[k * 8 + j]), acc);
    out[idx] = acc;
}

// ---------------- launch ----------------
static float* sym_addr_f(const void* sym) {
    void* p = nullptr;
    cudaGetSymbolAddress(&p, sym);
    return reinterpret_cast<float*>(p);
}
static int* sym_addr_i(const void* sym) {
    void* p = nullptr;
    cudaGetSymbolAddress(&p, sym);
    return reinterpret_cast<int*>(p);
}

extern "C" void kernel_launch(void* const* d_in, const int* in_sizes, int n_in,
                              void* d_out, int out_size)
{
    const float* x_user  = (const float*)d_in[0];
    const float* x_item  = (const float*)d_in[1];
    const int*   ei_u2i  = (const int*)d_in[2];
    const int*   ei_i2u  = (const int*)d_in[3];
    const float* enc_uw  = (const float*)d_in[4];
    const float* enc_ub  = (const float*)d_in[5];
    const float* enc_iw  = (const float*)d_in[6];
    const float* enc_ib  = (const float*)d_in[7];
    const float* L[12];
    for (int i = 0; i < 12; i++) L[i] = (const float*)d_in[8 + i];
    const float* head_w1 = (const float*)d_in[20];
    const float* head_b1 = (const float*)d_in[21];
    const float* head_w2 = (const float*)d_in[22];
    const float* head_b2 = (const float*)d_in[23];
    float* out = (float*)d_out;

    float* hu    = sym_addr_f(g_hu);
    float* hi    = sym_addr_f(g_hi);
    float* agg   = sym_addr_f(g_agg);
    float* z     = sym_addr_f(g_z);
    float* agg_i = agg;
    float* agg_u = agg + (size_t)NI * HD;

    int* deg      = sym_addr_i(g_deg);
    int* rowptr_i = sym_addr_i(g_rowptr_i);
    int* rowptr_u = sym_addr_i(g_rowptr_u);
    int* fill     = sym_addr_i(g_fill);
    int* esrc_i   = sym_addr_i(g_esrc_i);
    int* esrc_u   = sym_addr_i(g_esrc_u);

    const int EB = (NE + 255) / 256;

    // ---- CSR build (both relations, reused by both layers) ----
    zero_kernel<<<((NI + NU) / 4 + 255) / 256, 256>>>((float4*)deg, (NI + NU) / 4);
    hist_kernel<<<EB, 256>>>(ei_u2i + NE, deg, NE);           // item degrees
    hist_kernel<<<EB, 256>>>(ei_i2u + NE, deg + NI, NE);      // user degrees
    scan_kernel<<<1, 1024>>>(deg,      rowptr_i, NI);
    scan_kernel<<<1, 1024>>>(deg + NI, rowptr_u, NU);
    copy_kernel<<<(NI + 255) / 256, 256>>>(rowptr_i, fill, NI);
    copy_kernel<<<(NU + 255) / 256, 256>>>(rowptr_u, fill + NI, NU);
    fill_kernel<<<EB, 256>>>(ei_u2i, fill,      esrc_i, NE);
    fill_kernel<<<EB, 256>>>(ei_i2u, fill + NI, esrc_u, NE);

    // ---- encoders ----
    mlp_relu_kernel<64, 128><<<(NU + 63) / 64, 128>>>(x_user, enc_uw, enc_ub, hu, NU);
    mlp_relu_kernel<32, 128><<<(NI + 63) / 64, 128>>>(x_item, enc_iw, enc_ib, hi, NI);

    const int GB_I = (NI * 32 + 255) / 256;
    const int GB_U = (NU * 32 + 255) / 256;

    for (int l = 0; l < 2; l++) {
        const float* wl_ui = L[l * 6 + 0];
        const float* bl_ui = L[l * 6 + 1];
        const float* wr_ui = L[l * 6 + 2];
        const float* wl_iu = L[l * 6 + 3];
        const float* bl_iu = L[l * 6 + 4];
        const float* wr_iu = L[l * 6 + 5];

        // both gathers read OLD hu/hi before any in-place update
        gather_mean_kernel<<<GB_I, 256>>>(hu, rowptr_i, esrc_i, agg_i, NI);
        gather_mean_kernel<<<GB_U, 256>>>(hi, rowptr_u, esrc_u, agg_u, NU);
        // in-place: h_new = relu(norm(...)) + h_old
        combine_kernel<<<(NI + 63) / 64, 128>>>(agg_i, hi, wl_ui, bl_ui, wr_ui, NI);
        combine_kernel<<<(NU + 63) / 64, 128>>>(agg_u, hu, wl_iu, bl_iu, wr_iu, NU);
    }

    // ---- head ----
    mlp_relu_kernel<128, 64><<<(NU + 127) / 128, 128>>>(hu, head_w1, head_b1, z, NU);
    head2_kernel<<<(NU * 8 + 255) / 256, 256>>>(z, head_w2, head_b2, out, NU);
}

// round 9
// speedup vs baseline: 1.4502x; 1.0997x over previous
#include <cuda_runtime.h>
#include <cuda_bf16.h>
#include <cstdint>

#define NU 50000
#define NI 50000
#define NE 800000
#define HD 128
#define NN (NI + NU)

typedef unsigned long long u64;

// ---------------- f32x2 packed-FMA helpers (Blackwell FFMA2) ----------------
__device__ __forceinline__ u64 pk2(float v) {
    u64 r; asm("mov.b64 %0, {%1,%1};" : "=l"(r) : "f"(v)); return r;
}
__device__ __forceinline__ void fma2(u64& d, u64 a, u64 b) {
    asm("fma.rn.f32x2 %0, %1, %2, %3;" : "=l"(d) : "l"(a), "l"(b), "l"(d));
}
__device__ __forceinline__ float2 up2(u64 v) {
    float2 f; asm("mov.b64 {%0,%1}, %2;" : "=f"(f.x), "=f"(f.y) : "l"(v)); return f;
}

// ---------------- device scratch ----------------
__device__ __align__(16) float g_hu[(size_t)NU * HD];
__device__ __align__(16) float g_hi[(size_t)NI * HD];
__device__ __align__(16) float g_agg[(size_t)NN * HD]; // [agg_item | agg_user]
__device__ __align__(16) float g_z[(size_t)NU * 64];

__device__ __align__(16) int g_deg[NN];         // [deg_item | deg_user]
__device__ __align__(16) int g_rowptr[NN + 1];  // combined CSR rowptr
__device__ __align__(16) int g_fill[NN];        // fill cursors
__device__ __align__(16) int g_bsums[128];      // block sums for 2-level scan
__device__ __align__(16) int g_esrc[2 * NE];    // combined grouped edge sources

// ---------------- zero ----------------
__global__ void zero_kernel(float4* __restrict__ p, int n4) {
    int i = blockIdx.x * blockDim.x + threadIdx.x;
    if (i < n4) p[i] = make_float4(0.f, 0.f, 0.f, 0.f);
}

// ---------------- CSR: histogram ----------------
__global__ void hist_kernel(const int* __restrict__ dst, int* __restrict__ deg, int ne) {
    int e = blockIdx.x * blockDim.x + threadIdx.x;
    if (e < ne) atomicAdd(&deg[dst[e]], 1);
}

// ---------------- CSR: two-level scan ----------------
// level 1: per-block (1024) exclusive scan, emit block totals
__global__ void __launch_bounds__(1024) scan1_kernel(
    const int* __restrict__ deg, int* __restrict__ rowptr, int* __restrict__ bsums, int n)
{
    __shared__ int ws[32];
    const int tid = threadIdx.x, lane = tid & 31, wid = tid >> 5;
    int i = blockIdx.x * 1024 + tid;
    int v = (i < n) ? deg[i] : 0;
    int x = v;
#pragma unroll
    for (int off = 1; off < 32; off <<= 1) {
        int y = __shfl_up_sync(0xffffffffu, x, off);
        if (lane >= off) x += y;
    }
    if (lane == 31) ws[wid] = x;
    __syncthreads();
    if (tid < 32) {
        int s = ws[tid];
#pragma unroll
        for (int off = 1; off < 32; off <<= 1) {
            int y = __shfl_up_sync(0xffffffffu, s, off);
            if (tid >= off) s += y;
        }
        ws[tid] = s;
    }
    __syncthreads();
    int prev = wid ? ws[wid - 1] : 0;
    if (i < n) rowptr[i] = prev + x - v;
    if (tid == 1023) bsums[blockIdx.x] = prev + x;
}

// level 2: in-place exclusive scan of <=1024 block sums
__global__ void __launch_bounds__(1024) scan2_kernel(int* __restrict__ data, int n) {
    __shared__ int ws[32];
    const int tid = threadIdx.x, lane = tid & 31, wid = tid >> 5;
    int v = (tid < n) ? data[tid] : 0;
    int x = v;
#pragma unroll
    for (int off = 1; off < 32; off <<= 1) {
        int y = __shfl_up_sync(0xffffffffu, x, off);
        if (lane >= off) x += y;
    }
    if (lane == 31) ws[wid] = x;
    __syncthreads();
    if (tid < 32) {
        int s = ws[tid];
#pragma unroll
        for (int off = 1; off < 32; off <<= 1) {
            int y = __shfl_up_sync(0xffffffffu, s, off);
            if (tid >= off) s += y;
        }
        ws[tid] = s;
    }
    __syncthreads();
    int prev = wid ? ws[wid - 1] : 0;
    if (tid < n) data[tid] = prev + x - v;
}

// level 3: add block offsets; also write fill cursor + sentinel
__global__ void scan3_kernel(int* __restrict__ rowptr, int* __restrict__ fill,
                             const int* __restrict__ bsums, int n, int total)
{
    int i = blockIdx.x * blockDim.x + threadIdx.x;
    if (i < n) {
        int v = rowptr[i] + bsums[i >> 10];
        rowptr[i] = v;
        fill[i] = v;
    }
    if (i == 0) rowptr[n] = total;
}

// ---------------- CSR: fill edge-source buckets ----------------
__global__ void fill_kernel(const int* __restrict__ ei, int* __restrict__ cursor,
                            int* __restrict__ esrc, int ne)
{
    int e = blockIdx.x * blockDim.x + threadIdx.x;
    if (e < ne) {
        int d = ei[ne + e];
        int p = atomicAdd(&cursor[d], 1);
        esrc[p] = ei[e];
    }
}

// ---------------- gather mean aggregation: one warp per dst node ----------------
__global__ void __launch_bounds__(256) gather_mean_kernel(
    const float* __restrict__ src_feat, const int* __restrict__ rowptr,
    const int* __restrict__ esrc, float* __restrict__ agg, int n)
{
    int node = (blockIdx.x * blockDim.x + threadIdx.x) >> 5;
    int lane = threadIdx.x & 31;
    if (node >= n) return;
    int beg = __ldg(&rowptr[node]);
    int end = __ldg(&rowptr[node + 1]);
    float4 acc = make_float4(0.f, 0.f, 0.f, 0.f);
    int e = beg;
    for (; e + 4 <= end; e += 4) {
        int s0 = __ldg(&esrc[e]);
        int s1 = __ldg(&esrc[e + 1]);
        int s2 = __ldg(&esrc[e + 2]);
        int s3 = __ldg(&esrc[e + 3]);
        float4 v0 = reinterpret_cast<const float4*>(src_feat + (size_t)s0 * HD)[lane];
        float4 v1 = reinterpret_cast<const float4*>(src_feat + (size_t)s1 * HD)[lane];
        float4 v2 = reinterpret_cast<const float4*>(src_feat + (size_t)s2 * HD)[lane];
        float4 v3 = reinterpret_cast<const float4*>(src_feat + (size_t)s3 * HD)[lane];
        acc.x += (v0.x + v1.x) + (v2.x + v3.x);
        acc.y += (v0.y + v1.y) + (v2.y + v3.y);
        acc.z += (v0.z + v1.z) + (v2.z + v3.z);
        acc.w += (v0.w + v1.w) + (v2.w + v3.w);
    }
    for (; e < end; e++) {
        int s = __ldg(&esrc[e]);
        float4 v = reinterpret_cast<const float4*>(src_feat + (size_t)s * HD)[lane];
        acc.x += v.x; acc.y += v.y; acc.z += v.z; acc.w += v.w;
    }
    float inv = 1.0f / fmaxf((float)(end - beg), 1.0f);
    acc.x *= inv; acc.y *= inv; acc.z *= inv; acc.w *= inv;
    reinterpret_cast<float4*>(agg + (size_t)node * HD)[lane] = acc;
}

// ---------------- fused SAGE combine (FFMA2 inner loop) ----------------
// h[r] = relu( L2norm(agg[r] @ Wl + bl + h[r] @ Wr) ) + h[r]
// BM=64, BN=128, BK=16, 128 threads, 8x8 tile per thread (packed as 8x4 f32x2).
__global__ void __launch_bounds__(128) combine_kernel(
    const float* __restrict__ agg, float* __restrict__ h,
    const float* __restrict__ wl, const float* __restrict__ bl,
    const float* __restrict__ wr, int n)
{
    __shared__ __align__(16) float As[16 * 64];
    __shared__ __align__(16) float Xs[16 * 64];
    __shared__ __align__(16) float Wls[16 * 128];
    __shared__ __align__(16) float Wrs[16 * 128];

    const int tid  = threadIdx.x;
    const int tx   = tid & 15;
    const int ty   = tid >> 4;
    const int row0 = blockIdx.x * 64;

    u64 acc[8][4];
#pragma unroll
    for (int i = 0; i < 8; i++)
#pragma unroll
        for (int j = 0; j < 4; j++) acc[i][j] = 0ull;

    const int lrow  = tid >> 1;
    const int lhalf = tid & 1;
    const int grow  = min(row0 + lrow, n - 1);

    for (int kc = 0; kc < 8; kc++) {
        const int k0 = kc * 16;
        {
            const float4* sl = reinterpret_cast<const float4*>(wl + k0 * 128);
            const float4* sr = reinterpret_cast<const float4*>(wr + k0 * 128);
            float4* dl = reinterpret_cast<float4*>(Wls);
            float4* dr = reinterpret_cast<float4*>(Wrs);
#pragma unroll
            for (int i = 0; i < 4; i++) {
                dl[tid + i * 128] = sl[tid + i * 128];
                dr[tid + i * 128] = sr[tid + i * 128];
            }
        }
        {
            const float* ap = agg + (size_t)grow * HD + k0 + lhalf * 8;
            const float* xp = h   + (size_t)grow * HD + k0 + lhalf * 8;
            float4 a0 = *reinterpret_cast<const float4*>(ap);
            float4 a1 = *reinterpret_cast<const float4*>(ap + 4);
            float4 x0 = *reinterpret_cast<const float4*>(xp);
            float4 x1 = *reinterpret_cast<const float4*>(xp + 4);
            int kb = lhalf * 8;
            As[(kb + 0) * 64 + lrow] = a0.x;
            As[(kb + 1) * 64 + lrow] = a0.y;
            As[(kb + 2) * 64 + lrow] = a0.z;
            As[(kb + 3) * 64 + lrow] = a0.w;
            As[(kb + 4) * 64 + lrow] = a1.x;
            As[(kb + 5) * 64 + lrow] = a1.y;
            As[(kb + 6) * 64 + lrow] = a1.z;
            As[(kb + 7) * 64 + lrow] = a1.w;
            Xs[(kb + 0) * 64 + lrow] = x0.x;
            Xs[(kb + 1) * 64 + lrow] = x0.y;
            Xs[(kb + 2) * 64 + lrow] = x0.z;
            Xs[(kb + 3) * 64 + lrow] = x0.w;
            Xs[(kb + 4) * 64 + lrow] = x1.x;
            Xs[(kb + 5) * 64 + lrow] = x1.y;
            Xs[(kb + 6) * 64 + lrow] = x1.z;
            Xs[(kb + 7) * 64 + lrow] = x1.w;
        }
        __syncthreads();

#pragma unroll 2
        for (int k = 0; k < 16; k++) {
            float4 a0 = *reinterpret_cast<float4*>(&As[k * 64 + ty * 8]);
            float4 a1 = *reinterpret_cast<float4*>(&As[k * 64 + ty * 8 + 4]);
            float4 x0 = *reinterpret_cast<float4*>(&Xs[k * 64 + ty * 8]);
            float4 x1 = *reinterpret_cast<float4*>(&Xs[k * 64 + ty * 8 + 4]);
            ulonglong2 L0 = *reinterpret_cast<ulonglong2*>(&Wls[k * 128 + tx * 8]);
            ulonglong2 L1 = *reinterpret_cast<ulonglong2*>(&Wls[k * 128 + tx * 8 + 4]);
            ulonglong2 R0 = *reinterpret_cast<ulonglong2*>(&Wrs[k * 128 + tx * 8]);
            ulonglong2 R1 = *reinterpret_cast<ulonglong2*>(&Wrs[k * 128 + tx * 8 + 4]);
            u64 lv[4] = {L0.x, L0.y, L1.x, L1.y};
            u64 rv[4] = {R0.x, R0.y, R1.x, R1.y};
            float av[8] = {a0.x, a0.y, a0.z, a0.w, a1.x, a1.y, a1.z, a1.w};
            float xv[8] = {x0.x, x0.y, x0.z, x0.w, x1.x, x1.y, x1.z, x1.w};
#pragma unroll
            for (int i = 0; i < 8; i++) {
                u64 ap2 = pk2(av[i]);
                u64 xp2 = pk2(xv[i]);
#pragma unroll
                for (int j = 0; j < 4; j++) {
                    fma2(acc[i][j], ap2, lv[j]);
                    fma2(acc[i][j], xp2, rv[j]);
                }
            }
        }
        __syncthreads();
    }

    float bias[8];
#pragma unroll
    for (int j = 0; j < 8; j++) bias[j] = __ldg(&bl[tx * 8 + j]);

#pragma unroll
    for (int i = 0; i < 8; i++) {
        float v[8];
        float ss = 0.f;
#pragma unroll
        for (int j = 0; j < 4; j++) {
            float2 t = up2(acc[i][j]);
            v[2 * j]     = t.x + bias[2 * j];
            v[2 * j + 1] = t.y + bias[2 * j + 1];
            ss = fmaf(v[2 * j], v[2 * j], ss);
            ss = fmaf(v[2 * j + 1], v[2 * j + 1], ss);
        }
#pragma unroll
        for (int m = 8; m >= 1; m >>= 1)
            ss += __shfl_xor_sync(0xffffffffu, ss, m, 16);
        float inv = 1.0f / fmaxf(sqrtf(ss), 1e-12f);
        int gr = row0 + ty * 8 + i;
        if (gr < n) {
            float* hp = h + (size_t)gr * HD + tx * 8;
            float4 h0 = *reinterpret_cast<float4*>(hp);
            float4 h1 = *reinterpret_cast<float4*>(hp + 4);
            float o[8] = {h0.x, h0.y, h0.z, h0.w, h1.x, h1.y, h1.z, h1.w};
#pragma unroll
            for (int j = 0; j < 8; j++) o[j] += fmaxf(v[j] * inv, 0.0f);
            *reinterpret_cast<float4*>(hp)     = make_float4(o[0], o[1], o[2], o[3]);
            *reinterpret_cast<float4*>(hp + 4) = make_float4(o[4], o[5], o[6], o[7]);
        }
    }
}

// ---------------- register-tiled dense + relu (FFMA2) ----------------
template<int K, int N>
__global__ void __launch_bounds__(128) mlp_relu_kernel(
    const float* __restrict__ x, const float* __restrict__ W,
    const float* __restrict__ b, float* __restrict__ out, int n)
{
    constexpr int TX = N / 8;
    constexpr int TY = 128 / TX;
    constexpr int BM = TY * 8;
    __shared__ __align__(16) float Xs[16 * BM];
    __shared__ __align__(16) float Ws[16 * N];

    const int tid  = threadIdx.x;
    const int tx   = tid % TX;
    const int ty   = tid / TX;
    const int row0 = blockIdx.x * BM;

    u64 acc[8][4];
#pragma unroll
    for (int i = 0; i < 8; i++)
#pragma unroll
        for (int j = 0; j < 4; j++) acc[i][j] = 0ull;

#pragma unroll 1
    for (int kc = 0; kc < K / 16; kc++) {
        const int k0 = kc * 16;
#pragma unroll
        for (int i = tid; i < 16 * N / 4; i += 128)
            reinterpret_cast<float4*>(Ws)[i] =
                reinterpret_cast<const float4*>(W + (size_t)k0 * N)[i];
#pragma unroll
        for (int idx = tid; idx < BM * 2; idx += 128) {
            int r = idx >> 1, half = idx & 1;
            int gr = min(row0 + r, n - 1);
            const float* xp = x + (size_t)gr * K + k0 + half * 8;
            float4 x0 = *reinterpret_cast<const float4*>(xp);
            float4 x1 = *reinterpret_cast<const float4*>(xp + 4);
            int kb = half * 8;
            Xs[(kb + 0) * BM + r] = x0.x;
            Xs[(kb + 1) * BM + r] = x0.y;
            Xs[(kb + 2) * BM + r] = x0.z;
            Xs[(kb + 3) * BM + r] = x0.w;
            Xs[(kb + 4) * BM + r] = x1.x;
            Xs[(kb + 5) * BM + r] = x1.y;
            Xs[(kb + 6) * BM + r] = x1.z;
            Xs[(kb + 7) * BM + r] = x1.w;
        }
        __syncthreads();

#pragma unroll 2
        for (int k = 0; k < 16; k++) {
            float4 a0 = *reinterpret_cast<float4*>(&Xs[k * BM + ty * 8]);
            float4 a1 = *reinterpret_cast<float4*>(&Xs[k * BM + ty * 8 + 4]);
            ulonglong2 W0 = *reinterpret_cast<ulonglong2*>(&Ws[k * N + tx * 8]);
            ulonglong2 W1 = *reinterpret_cast<ulonglong2*>(&Ws[k * N + tx * 8 + 4]);
            u64 wv[4] = {W0.x, W0.y, W1.x, W1.y};
            float av[8] = {a0.x, a0.y, a0.z, a0.w, a1.x, a1.y, a1.z, a1.w};
#pragma unroll
            for (int i = 0; i < 8; i++) {
                u64 ap2 = pk2(av[i]);
#pragma unroll
                for (int j = 0; j < 4; j++)
                    fma2(acc[i][j], ap2, wv[j]);
            }
        }
        __syncthreads();
    }

    float bias[8];
#pragma unroll
    for (int j = 0; j < 8; j++) bias[j] = __ldg(&b[tx * 8 + j]);

#pragma unroll
    for (int i = 0; i < 8; i++) {
        int gr = row0 + ty * 8 + i;
        if (gr < n) {
            float o[8];
#pragma unroll
            for (int j = 0; j < 4; j++) {
                float2 t = up2(acc[i][j]);
                o[2 * j]     = fmaxf(t.x + bias[2 * j], 0.0f);
                o[2 * j + 1] = fmaxf(t.y + bias[2 * j + 1], 0.0f);
            }
            float* op = out + (size_t)gr * N + tx * 8;
            *reinterpret_cast<float4*>(op)     = make_float4(o[0], o[1], o[2], o[3]);
            *reinterpret_cast<float4*>(op + 4) = make_float4(o[4], o[5], o[6], o[7]);
        }
    }
}

// ---------------- head layer 2 (no relu): [n,64] @ [64,8] + b ----------------
__global__ void __launch_bounds__(256) head2_kernel(
    const float* __restrict__ z, const float* __restrict__ w2,
    const float* __restrict__ b2, float* __restrict__ out, int n)
{
    int idx = blockIdx.x * blockDim.x + threadIdx.x;
    if (idx >= n * 8) return;
    int row = idx >> 3;
    int j = idx & 7;
    float acc = __ldg(&b2[j]);
    const float* zr = z + (size_t)row * 64;
#pragma unroll
    for (int k = 0; k < 64; k++) acc = fmaf(zr[k], __ldg(&w2[k * 8 + j]), acc);
    out[idx] = acc;
}

// ---------------- launch ----------------
static float* sym_addr_f(const void* sym) {
    void* p = nullptr;
    cudaGetSymbolAddress(&p, sym);
    return reinterpret_cast<float*>(p);
}
static int* sym_addr_i(const void* sym) {
    void* p = nullptr;
    cudaGetSymbolAddress(&p, sym);
    return reinterpret_cast<int*>(p);
}

extern "C" void kernel_launch(void* const* d_in, const int* in_sizes, int n_in,
                              void* d_out, int out_size)
{
    const float* x_user  = (const float*)d_in[0];
    const float* x_item  = (const float*)d_in[1];
    const int*   ei_u2i  = (const int*)d_in[2];
    const int*   ei_i2u  = (const int*)d_in[3];
    const float* enc_uw  = (const float*)d_in[4];
    const float* enc_ub  = (const float*)d_in[5];
    const float* enc_iw  = (const float*)d_in[6];
    const float* enc_ib  = (const float*)d_in[7];
    const float* L[12];
    for (int i = 0; i < 12; i++) L[i] = (const float*)d_in[8 + i];
    const float* head_w1 = (const float*)d_in[20];
    const float* head_b1 = (const float*)d_in[21];
    const float* head_w2 = (const float*)d_in[22];
    const float* head_b2 = (const float*)d_in[23];
    float* out = (float*)d_out;

    float* hu    = sym_addr_f(g_hu);
    float* hi    = sym_addr_f(g_hi);
    float* agg   = sym_addr_f(g_agg);
    float* z     = sym_addr_f(g_z);
    float* agg_i = agg;
    float* agg_u = agg + (size_t)NI * HD;

    int* deg    = sym_addr_i(g_deg);
    int* rowptr = sym_addr_i(g_rowptr);
    int* fill   = sym_addr_i(g_fill);
    int* bsums  = sym_addr_i(g_bsums);
    int* esrc   = sym_addr_i(g_esrc);

    const int EB = (NE + 255) / 256;
    const int NB1 = (NN + 1023) / 1024;   // 98 blocks

    // ---- CSR build (combined, reused by both layers) ----
    zero_kernel<<<(NN / 4 + 255) / 256, 256>>>((float4*)deg, NN / 4);
    hist_kernel<<<EB, 256>>>(ei_u2i + NE, deg, NE);           // item degrees
    hist_kernel<<<EB, 256>>>(ei_i2u + NE, deg + NI, NE);      // user degrees
    scan1_kernel<<<NB1, 1024>>>(deg, rowptr, bsums, NN);
    scan2_kernel<<<1, 1024>>>(bsums, NB1);
    scan3_kernel<<<(NN + 255) / 256, 256>>>(rowptr, fill, bsums, NN, 2 * NE);
    fill_kernel<<<EB, 256>>>(ei_u2i, fill,      esrc, NE);
    fill_kernel<<<EB, 256>>>(ei_i2u, fill + NI, esrc, NE);

    // ---- encoders ----
    mlp_relu_kernel<64, 128><<<(NU + 63) / 64, 128>>>(x_user, enc_uw, enc_ub, hu, NU);
    mlp_relu_kernel<32, 128><<<(NI + 63) / 64, 128>>>(x_item, enc_iw, enc_ib, hi, NI);

    const int GB_I = (NI * 32 + 255) / 256;
    const int GB_U = (NU * 32 + 255) / 256;

    for (int l = 0; l < 2; l++) {
        const float* wl_ui = L[l * 6 + 0];
        const float* bl_ui = L[l * 6 + 1];
        const float* wr_ui = L[l * 6 + 2];
        const float* wl_iu = L[l * 6 + 3];
        const float* bl_iu = L[l * 6 + 4];
        const float* wr_iu = L[l * 6 + 5];

        // both gathers read OLD hu/hi before any in-place update
        gather_mean_kernel<<<GB_I, 256>>>(hu, rowptr,      esrc, agg_i, NI);
        gather_mean_kernel<<<GB_U, 256>>>(hi, rowptr + NI, esrc, agg_u, NU);
        // in-place: h_new = relu(norm(...)) + h_old
        combine_kernel<<<(NI + 63) / 64, 128>>>(agg_i, hi, wl_ui, bl_ui, wr_ui, NI);
        combine_kernel<<<(NU + 63) / 64, 128>>>(agg_u, hu, wl_iu, bl_iu, wr_iu, NU);
    }

    // ---- head ----
    mlp_relu_kernel<128, 64><<<(NU + 127) / 128, 128>>>(hu, head_w1, head_b1, z, NU);
    head2_kernel<<<(NU * 8 + 255) / 256, 256>>>(z, head_w2, head_b2, out, NU);
}

// round 10
// speedup vs baseline: 2.0754x; 1.4312x over previous
#include <cuda_runtime.h>
#include <cuda_bf16.h>
#include <cstdint>

#define NU 50000
#define NI 50000
#define NE 800000
#define HD 128
#define NN (NI + NU)

typedef unsigned long long u64;

// ---------------- f32x2 packed-FMA helpers (Blackwell FFMA2) ----------------
__device__ __forceinline__ u64 pk2(float v) {
    u64 r; asm("mov.b64 %0, {%1,%1};" : "=l"(r) : "f"(v)); return r;
}
__device__ __forceinline__ void fma2(u64& d, u64 a, u64 b) {
    asm("fma.rn.f32x2 %0, %1, %2, %3;" : "=l"(d) : "l"(a), "l"(b), "l"(d));
}
__device__ __forceinline__ float2 up2(u64 v) {
    float2 f; asm("mov.b64 {%0,%1}, %2;" : "=f"(f.x), "=f"(f.y) : "l"(v)); return f;
}

// ---------------- device scratch ----------------
__device__ __align__(16) float g_hu[(size_t)NU * HD];
__device__ __align__(16) float g_hi[(size_t)NI * HD];
__device__ __align__(16) float g_agg[(size_t)NN * HD]; // [agg_item | agg_user]
__device__ __align__(16) float g_z[(size_t)NU * 64];

__device__ __align__(16) int g_deg[NN];         // [deg_item | deg_user]
__device__ __align__(16) int g_rowptr[NN + 1];  // combined CSR rowptr
__device__ __align__(16) int g_fill[NN];        // fill cursors
__device__ __align__(16) int g_bsums[128];      // block sums for 2-level scan
__device__ __align__(16) int g_esrc[2 * NE];    // combined grouped edge sources

// ---------------- zero ----------------
__global__ void zero_kernel(float4* __restrict__ p, int n4) {
    int i = blockIdx.x * blockDim.x + threadIdx.x;
    if (i < n4) p[i] = make_float4(0.f, 0.f, 0.f, 0.f);
}

// ---------------- CSR: histogram over both relations (one launch) ----------------
__global__ void hist2_kernel(const int* __restrict__ ei_a, const int* __restrict__ ei_b,
                             int* __restrict__ deg)
{
    int e = blockIdx.x * blockDim.x + threadIdx.x;
    if (e < NE) {
        atomicAdd(&deg[ei_a[NE + e]], 1);            // item degrees
    } else if (e < 2 * NE) {
        atomicAdd(&deg[NI + ei_b[e]], 1);            // user degrees (e = NE + e')
    }
}

// ---------------- CSR: two-level scan ----------------
__global__ void __launch_bounds__(1024) scan1_kernel(
    const int* __restrict__ deg, int* __restrict__ rowptr, int* __restrict__ bsums, int n)
{
    __shared__ int ws[32];
    const int tid = threadIdx.x, lane = tid & 31, wid = tid >> 5;
    int i = blockIdx.x * 1024 + tid;
    int v = (i < n) ? deg[i] : 0;
    int x = v;
#pragma unroll
    for (int off = 1; off < 32; off <<= 1) {
        int y = __shfl_up_sync(0xffffffffu, x, off);
        if (lane >= off) x += y;
    }
    if (lane == 31) ws[wid] = x;
    __syncthreads();
    if (tid < 32) {
        int s = ws[tid];
#pragma unroll
        for (int off = 1; off < 32; off <<= 1) {
            int y = __shfl_up_sync(0xffffffffu, s, off);
            if (tid >= off) s += y;
        }
        ws[tid] = s;
    }
    __syncthreads();
    int prev = wid ? ws[wid - 1] : 0;
    if (i < n) rowptr[i] = prev + x - v;
    if (tid == 1023) bsums[blockIdx.x] = prev + x;
}

__global__ void __launch_bounds__(1024) scan2_kernel(int* __restrict__ data, int n) {
    __shared__ int ws[32];
    const int tid = threadIdx.x, lane = tid & 31, wid = tid >> 5;
    int v = (tid < n) ? data[tid] : 0;
    int x = v;
#pragma unroll
    for (int off = 1; off < 32; off <<= 1) {
        int y = __shfl_up_sync(0xffffffffu, x, off);
        if (lane >= off) x += y;
    }
    if (lane == 31) ws[wid] = x;
    __syncthreads();
    if (tid < 32) {
        int s = ws[tid];
#pragma unroll
        for (int off = 1; off < 32; off <<= 1) {
            int y = __shfl_up_sync(0xffffffffu, s, off);
            if (tid >= off) s += y;
        }
        ws[tid] = s;
    }
    __syncthreads();
    int prev = wid ? ws[wid - 1] : 0;
    if (tid < n) data[tid] = prev + x - v;
}

__global__ void scan3_kernel(int* __restrict__ rowptr, int* __restrict__ fill,
                             const int* __restrict__ bsums, int n, int total)
{
    int i = blockIdx.x * blockDim.x + threadIdx.x;
    if (i < n) {
        int v = rowptr[i] + bsums[i >> 10];
        rowptr[i] = v;
        fill[i] = v;
    }
    if (i == 0) rowptr[n] = total;
}

// ---------------- CSR: fill edge-source buckets (both relations, one launch) ----------------
__global__ void fill2_kernel(const int* __restrict__ ei_a, const int* __restrict__ ei_b,
                             int* __restrict__ cursor, int* __restrict__ esrc)
{
    int e = blockIdx.x * blockDim.x + threadIdx.x;
    if (e < NE) {
        int d = ei_a[NE + e];
        int p = atomicAdd(&cursor[d], 1);
        esrc[p] = ei_a[e];
    } else if (e < 2 * NE) {
        int d = ei_b[e];                      // e = NE + e' -> ei_b[NE + e'] == ei_b[e]
        int p = atomicAdd(&cursor[NI + d], 1);
        esrc[p] = ei_b[e - NE];
    }
}

// ---------------- gather mean: one warp per dst node; node<split reads srcA else srcB ----
__global__ void __launch_bounds__(256) gather_mean_kernel(
    const float* __restrict__ srcA, const float* __restrict__ srcB,
    const int* __restrict__ rowptr, const int* __restrict__ esrc,
    float* __restrict__ agg, int n, int split)
{
    int node = (blockIdx.x * blockDim.x + threadIdx.x) >> 5;
    int lane = threadIdx.x & 31;
    if (node >= n) return;
    const float* src_feat = (node < split) ? srcA : srcB;
    int beg = __ldg(&rowptr[node]);
    int end = __ldg(&rowptr[node + 1]);
    float4 acc = make_float4(0.f, 0.f, 0.f, 0.f);
    int e = beg;
    for (; e + 4 <= end; e += 4) {
        int s0 = __ldg(&esrc[e]);
        int s1 = __ldg(&esrc[e + 1]);
        int s2 = __ldg(&esrc[e + 2]);
        int s3 = __ldg(&esrc[e + 3]);
        float4 v0 = reinterpret_cast<const float4*>(src_feat + (size_t)s0 * HD)[lane];
        float4 v1 = reinterpret_cast<const float4*>(src_feat + (size_t)s1 * HD)[lane];
        float4 v2 = reinterpret_cast<const float4*>(src_feat + (size_t)s2 * HD)[lane];
        float4 v3 = reinterpret_cast<const float4*>(src_feat + (size_t)s3 * HD)[lane];
        acc.x += (v0.x + v1.x) + (v2.x + v3.x);
        acc.y += (v0.y + v1.y) + (v2.y + v3.y);
        acc.z += (v0.z + v1.z) + (v2.z + v3.z);
        acc.w += (v0.w + v1.w) + (v2.w + v3.w);
    }
    for (; e < end; e++) {
        int s = __ldg(&esrc[e]);
        float4 v = reinterpret_cast<const float4*>(src_feat + (size_t)s * HD)[lane];
        acc.x += v.x; acc.y += v.y; acc.z += v.z; acc.w += v.w;
    }
    float inv = 1.0f / fmaxf((float)(end - beg), 1.0f);
    acc.x *= inv; acc.y *= inv; acc.z *= inv; acc.w *= inv;
    reinterpret_cast<float4*>(agg + (size_t)node * HD)[lane] = acc;
}

// ---------------- fused SAGE combine (FFMA2 inner loop) ----------------
// h[r] = relu( L2norm(agg[r] @ Wl + bl + h[r] @ Wr) ) + h[r]
__global__ void __launch_bounds__(128) combine_kernel(
    const float* __restrict__ agg, float* __restrict__ h,
    const float* __restrict__ wl, const float* __restrict__ bl,
    const float* __restrict__ wr, int n)
{
    __shared__ __align__(16) float As[16 * 64];
    __shared__ __align__(16) float Xs[16 * 64];
    __shared__ __align__(16) float Wls[16 * 128];
    __shared__ __align__(16) float Wrs[16 * 128];

    const int tid  = threadIdx.x;
    const int tx   = tid & 15;
    const int ty   = tid >> 4;
    const int row0 = blockIdx.x * 64;

    u64 acc[8][4];
#pragma unroll
    for (int i = 0; i < 8; i++)
#pragma unroll
        for (int j = 0; j < 4; j++) acc[i][j] = 0ull;

    const int lrow  = tid >> 1;
    const int lhalf = tid & 1;
    const int grow  = min(row0 + lrow, n - 1);

    for (int kc = 0; kc < 8; kc++) {
        const int k0 = kc * 16;
        {
            const float4* sl = reinterpret_cast<const float4*>(wl + k0 * 128);
            const float4* sr = reinterpret_cast<const float4*>(wr + k0 * 128);
            float4* dl = reinterpret_cast<float4*>(Wls);
            float4* dr = reinterpret_cast<float4*>(Wrs);
#pragma unroll
            for (int i = 0; i < 4; i++) {
                dl[tid + i * 128] = sl[tid + i * 128];
                dr[tid + i * 128] = sr[tid + i * 128];
            }
        }
        {
            const float* ap = agg + (size_t)grow * HD + k0 + lhalf * 8;
            const float* xp = h   + (size_t)grow * HD + k0 + lhalf * 8;
            float4 a0 = *reinterpret_cast<const float4*>(ap);
            float4 a1 = *reinterpret_cast<const float4*>(ap + 4);
            float4 x0 = *reinterpret_cast<const float4*>(xp);
            float4 x1 = *reinterpret_cast<const float4*>(xp + 4);
            int kb = lhalf * 8;
            As[(kb + 0) * 64 + lrow] = a0.x;
            As[(kb + 1) * 64 + lrow] = a0.y;
            As[(kb + 2) * 64 + lrow] = a0.z;
            As[(kb + 3) * 64 + lrow] = a0.w;
            As[(kb + 4) * 64 + lrow] = a1.x;
            As[(kb + 5) * 64 + lrow] = a1.y;
            As[(kb + 6) * 64 + lrow] = a1.z;
            As[(kb + 7) * 64 + lrow] = a1.w;
            Xs[(kb + 0) * 64 + lrow] = x0.x;
            Xs[(kb + 1) * 64 + lrow] = x0.y;
            Xs[(kb + 2) * 64 + lrow] = x0.z;
            Xs[(kb + 3) * 64 + lrow] = x0.w;
            Xs[(kb + 4) * 64 + lrow] = x1.x;
            Xs[(kb + 5) * 64 + lrow] = x1.y;
            Xs[(kb + 6) * 64 + lrow] = x1.z;
            Xs[(kb + 7) * 64 + lrow] = x1.w;
        }
        __syncthreads();

#pragma unroll 2
        for (int k = 0; k < 16; k++) {
            float4 a0 = *reinterpret_cast<float4*>(&As[k * 64 + ty * 8]);
            float4 a1 = *reinterpret_cast<float4*>(&As[k * 64 + ty * 8 + 4]);
            float4 x0 = *reinterpret_cast<float4*>(&Xs[k * 64 + ty * 8]);
            float4 x1 = *reinterpret_cast<float4*>(&Xs[k * 64 + ty * 8 + 4]);
            ulonglong2 L0 = *reinterpret_cast<ulonglong2*>(&Wls[k * 128 + tx * 8]);
            ulonglong2 L1 = *reinterpret_cast<ulonglong2*>(&Wls[k * 128 + tx * 8 + 4]);
            ulonglong2 R0 = *reinterpret_cast<ulonglong2*>(&Wrs[k * 128 + tx * 8]);
            ulonglong2 R1 = *reinterpret_cast<ulonglong2*>(&Wrs[k * 128 + tx * 8 + 4]);
            u64 lv[4] = {L0.x, L0.y, L1.x, L1.y};
            u64 rv[4] = {R0.x, R0.y, R1.x, R1.y};
            float av[8] = {a0.x, a0.y, a0.z, a0.w, a1.x, a1.y, a1.z, a1.w};
            float xv[8] = {x0.x, x0.y, x0.z, x0.w, x1.x, x1.y, x1.z, x1.w};
#pragma unroll
            for (int i = 0; i < 8; i++) {
                u64 ap2 = pk2(av[i]);
                u64 xp2 = pk2(xv[i]);
#pragma unroll
                for (int j = 0; j < 4; j++) {
                    fma2(acc[i][j], ap2, lv[j]);
                    fma2(acc[i][j], xp2, rv[j]);
                }
            }
        }
        __syncthreads();
    }

    float bias[8];
#pragma unroll
    for (int j = 0; j < 8; j++) bias[j] = __ldg(&bl[tx * 8 + j]);

#pragma unroll
    for (int i = 0; i < 8; i++) {
        float v[8];
        float ss = 0.f;
#pragma unroll
        for (int j = 0; j < 4; j++) {
            float2 t = up2(acc[i][j]);
            v[2 * j]     = t.x + bias[2 * j];
            v[2 * j + 1] = t.y + bias[2 * j + 1];
            ss = fmaf(v[2 * j], v[2 * j], ss);
            ss = fmaf(v[2 * j + 1], v[2 * j + 1], ss);
        }
#pragma unroll
        for (int m = 8; m >= 1; m >>= 1)
            ss += __shfl_xor_sync(0xffffffffu, ss, m, 16);
        float inv = 1.0f / fmaxf(sqrtf(ss), 1e-12f);
        int gr = row0 + ty * 8 + i;
        if (gr < n) {
            float* hp = h + (size_t)gr * HD + tx * 8;
            float4 h0 = *reinterpret_cast<float4*>(hp);
            float4 h1 = *reinterpret_cast<float4*>(hp + 4);
            float o[8] = {h0.x, h0.y, h0.z, h0.w, h1.x, h1.y, h1.z, h1.w};
#pragma unroll
            for (int j = 0; j < 8; j++) o[j] += fmaxf(v[j] * inv, 0.0f);
            *reinterpret_cast<float4*>(hp)     = make_float4(o[0], o[1], o[2], o[3]);
            *reinterpret_cast<float4*>(hp + 4) = make_float4(o[4], o[5], o[6], o[7]);
        }
    }
}

// ---------------- register-tiled dense + relu (FFMA2) ----------------
template<int K, int N>
__global__ void __launch_bounds__(128) mlp_relu_kernel(
    const float* __restrict__ x, const float* __restrict__ W,
    const float* __restrict__ b, float* __restrict__ out, int n)
{
    constexpr int TX = N / 8;
    constexpr int TY = 128 / TX;
    constexpr int BM = TY * 8;
    __shared__ __align__(16) float Xs[16 * BM];
    __shared__ __align__(16) float Ws[16 * N];

    const int tid  = threadIdx.x;
    const int tx   = tid % TX;
    const int ty   = tid / TX;
    const int row0 = blockIdx.x * BM;

    u64 acc[8][4];
#pragma unroll
    for (int i = 0; i < 8; i++)
#pragma unroll
        for (int j = 0; j < 4; j++) acc[i][j] = 0ull;

#pragma unroll 1
    for (int kc = 0; kc < K / 16; kc++) {
        const int k0 = kc * 16;
#pragma unroll
        for (int i = tid; i < 16 * N / 4; i += 128)
            reinterpret_cast<float4*>(Ws)[i] =
                reinterpret_cast<const float4*>(W + (size_t)k0 * N)[i];
#pragma unroll
        for (int idx = tid; idx < BM * 2; idx += 128) {
            int r = idx >> 1, half = idx & 1;
            int gr = min(row0 + r, n - 1);
            const float* xp = x + (size_t)gr * K + k0 + half * 8;
            float4 x0 = *reinterpret_cast<const float4*>(xp);
            float4 x1 = *reinterpret_cast<const float4*>(xp + 4);
            int kb = half * 8;
            Xs[(kb + 0) * BM + r] = x0.x;
            Xs[(kb + 1) * BM + r] = x0.y;
            Xs[(kb + 2) * BM + r] = x0.z;
            Xs[(kb + 3) * BM + r] = x0.w;
            Xs[(kb + 4) * BM + r] = x1.x;
            Xs[(kb + 5) * BM + r] = x1.y;
            Xs[(kb + 6) * BM + r] = x1.z;
            Xs[(kb + 7) * BM + r] = x1.w;
        }
        __syncthreads();

#pragma unroll 2
        for (int k = 0; k < 16; k++) {
            float4 a0 = *reinterpret_cast<float4*>(&Xs[k * BM + ty * 8]);
            float4 a1 = *reinterpret_cast<float4*>(&Xs[k * BM + ty * 8 + 4]);
            ulonglong2 W0 = *reinterpret_cast<ulonglong2*>(&Ws[k * N + tx * 8]);
            ulonglong2 W1 = *reinterpret_cast<ulonglong2*>(&Ws[k * N + tx * 8 + 4]);
            u64 wv[4] = {W0.x, W0.y, W1.x, W1.y};
            float av[8] = {a0.x, a0.y, a0.z, a0.w, a1.x, a1.y, a1.z, a1.w};
#pragma unroll
            for (int i = 0; i < 8; i++) {
                u64 ap2 = pk2(av[i]);
#pragma unroll
                for (int j = 0; j < 4; j++)
                    fma2(acc[i][j], ap2, wv[j]);
            }
        }
        __syncthreads();
    }

    float bias[8];
#pragma unroll
    for (int j = 0; j < 8; j++) bias[j] = __ldg(&b[tx * 8 + j]);

#pragma unroll
    for (int i = 0; i < 8; i++) {
        int gr = row0 + ty * 8 + i;
        if (gr < n) {
            float o[8];
#pragma unroll
            for (int j = 0; j < 4; j++) {
                float2 t = up2(acc[i][j]);
                o[2 * j]     = fmaxf(t.x + bias[2 * j], 0.0f);
                o[2 * j + 1] = fmaxf(t.y + bias[2 * j + 1], 0.0f);
            }
            float* op = out + (size_t)gr * N + tx * 8;
            *reinterpret_cast<float4*>(op)     = make_float4(o[0], o[1], o[2], o[3]);
            *reinterpret_cast<float4*>(op + 4) = make_float4(o[4], o[5], o[6], o[7]);
        }
    }
}

// ---------------- head layer 2 (no relu): [n,64] @ [64,8] + b ----------------
__global__ void __launch_bounds__(256) head2_kernel(
    const float* __restrict__ z, const float* __restrict__ w2,
    const float* __restrict__ b2, float* __restrict__ out, int n)
{
    int idx = blockIdx.x * blockDim.x + threadIdx.x;
    if (idx >= n * 8) return;
    int row = idx >> 3;
    int j = idx & 7;
    float acc = __ldg(&b2[j]);
    const float* zr = z + (size_t)row * 64;
#pragma unroll
    for (int k = 0; k < 64; k++) acc = fmaf(zr[k], __ldg(&w2[k * 8 + j]), acc);
    out[idx] = acc;
}

// ---------------- stream/event resources (created once at static init) ----------------
struct GraphRes {
    cudaStream_t s1;
    cudaEvent_t ev_start, ev_enc, ev_fork, ev_cu1;
    GraphRes() {
        cudaStreamCreateWithFlags(&s1, cudaStreamNonBlocking);
        cudaEventCreateWithFlags(&ev_start, cudaEventDisableTiming);
        cudaEventCreateWithFlags(&ev_enc,   cudaEventDisableTiming);
        cudaEventCreateWithFlags(&ev_fork,  cudaEventDisableTiming);
        cudaEventCreateWithFlags(&ev_cu1,   cudaEventDisableTiming);
    }
};
static GraphRes g_res;

// ---------------- launch ----------------
static float* sym_addr_f(const void* sym) {
    void* p = nullptr;
    cudaGetSymbolAddress(&p, sym);
    return reinterpret_cast<float*>(p);
}
static int* sym_addr_i(const void* sym) {
    void* p = nullptr;
    cudaGetSymbolAddress(&p, sym);
    return reinterpret_cast<int*>(p);
}

extern "C" void kernel_launch(void* const* d_in, const int* in_sizes, int n_in,
                              void* d_out, int out_size)
{
    const float* x_user  = (const float*)d_in[0];
    const float* x_item  = (const float*)d_in[1];
    const int*   ei_u2i  = (const int*)d_in[2];
    const int*   ei_i2u  = (const int*)d_in[3];
    const float* enc_uw  = (const float*)d_in[4];
    const float* enc_ub  = (const float*)d_in[5];
    const float* enc_iw  = (const float*)d_in[6];
    const float* enc_ib  = (const float*)d_in[7];
    const float* L[12];
    for (int i = 0; i < 12; i++) L[i] = (const float*)d_in[8 + i];
    const float* head_w1 = (const float*)d_in[20];
    const float* head_b1 = (const float*)d_in[21];
    const float* head_w2 = (const float*)d_in[22];
    const float* head_b2 = (const float*)d_in[23];
    float* out = (float*)d_out;

    float* hu    = sym_addr_f(g_hu);
    float* hi    = sym_addr_f(g_hi);
    float* agg   = sym_addr_f(g_agg);
    float* z     = sym_addr_f(g_z);
    float* agg_i = agg;
    float* agg_u = agg + (size_t)NI * HD;

    int* deg    = sym_addr_i(g_deg);
    int* rowptr = sym_addr_i(g_rowptr);
    int* fill   = sym_addr_i(g_fill);
    int* bsums  = sym_addr_i(g_bsums);
    int* esrc   = sym_addr_i(g_esrc);

    cudaStream_t s1 = g_res.s1;
    const int EB2 = (2 * NE + 255) / 256;
    const int NB1 = (NN + 1023) / 1024;   // 98 blocks

    // ---- fork: encoders on s1, CSR build on main ----
    cudaEventRecord(g_res.ev_start, 0);
    cudaStreamWaitEvent(s1, g_res.ev_start, 0);

    mlp_relu_kernel<64, 128><<<(NU + 63) / 64, 128, 0, s1>>>(x_user, enc_uw, enc_ub, hu, NU);
    mlp_relu_kernel<32, 128><<<(NI + 63) / 64, 128, 0, s1>>>(x_item, enc_iw, enc_ib, hi, NI);
    cudaEventRecord(g_res.ev_enc, s1);

    zero_kernel<<<(NN / 4 + 255) / 256, 256>>>((float4*)deg, NN / 4);
    hist2_kernel<<<EB2, 256>>>(ei_u2i, ei_i2u, deg);
    scan1_kernel<<<NB1, 1024>>>(deg, rowptr, bsums, NN);
    scan2_kernel<<<1, 1024>>>(bsums, NB1);
    scan3_kernel<<<(NN + 255) / 256, 256>>>(rowptr, fill, bsums, NN, 2 * NE);
    fill2_kernel<<<EB2, 256>>>(ei_u2i, ei_i2u, fill, esrc);

    // join: gathers need both encoders and CSR
    cudaStreamWaitEvent(0, g_res.ev_enc, 0);

    // ---- layer 1: both gathers in one launch (items read hu, users read hi) ----
    gather_mean_kernel<<<(NN * 32 + 255) / 256, 256>>>(hu, hi, rowptr, esrc, agg, NN, NI);

    // fork: c_u1 on s1 (writes hu; gather done so hu reads complete)
    cudaEventRecord(g_res.ev_fork, 0);
    cudaStreamWaitEvent(s1, g_res.ev_fork, 0);
    combine_kernel<<<(NU + 63) / 64, 128, 0, s1>>>(agg_u, hu, L[3], L[4], L[5], NU);
    cudaEventRecord(g_res.ev_cu1, s1);

    // main: c_i1 (writes hi), then layer-2 user gather (reads hi1)
    combine_kernel<<<(NI + 63) / 64, 128>>>(agg_i, hi, L[0], L[1], L[2], NI);
    gather_mean_kernel<<<(NU * 32 + 255) / 256, 256>>>(nullptr, hi, rowptr + NI, esrc, agg_u, NU, 0);

    // join: c_u2 needs agg_u (main) + hu1 (s1)
    cudaStreamWaitEvent(0, g_res.ev_cu1, 0);

    // ---- layer 2: only the user path feeds the head (item update is dead code) ----
    combine_kernel<<<(NU + 63) / 64, 128>>>(agg_u, hu, L[9], L[10], L[11], NU);

    // ---- head ----
    mlp_relu_kernel<128, 64><<<(NU + 127) / 128, 128>>>(hu, head_w1, head_b1, z, NU);
    head2_kernel<<<(NU * 8 + 255) / 256, 256>>>(z, head_w2, head_b2, out, NU);
}